// round 2
// baseline (speedup 1.0000x reference)
#include <cuda_runtime.h>

#define CC   64
#define CC2  32
#define TT   8
#define PP   2304
#define NBT  16

typedef unsigned long long ull;

// scratch: theta^T [bt][p][32], phi^T [bt][p][32], v=(out_w @ x) [bt][p][64]
__device__ float g_theta[NBT * PP * CC2];
__device__ float g_phi  [NBT * PP * CC2];
__device__ float g_v    [NBT * PP * CC ];

__device__ __forceinline__ float ex2(float x) {
    float y;
    asm("ex2.approx.ftz.f32 %0, %1;" : "=f"(y) : "f"(x));
    return y;
}
#define FMA2(d, a, b) asm("fma.rn.f32x2 %0, %1, %2, %0;" : "+l"(d) : "l"(a), "l"(b))
__device__ __forceinline__ float f2lo(ull v) { return __uint_as_float((unsigned)v); }
__device__ __forceinline__ float f2hi(ull v) { return __uint_as_float((unsigned)(v >> 32)); }

// ---------------------------------------------------------------------------
// Kernel A: per-(b,t) channel projections; out_w folded into V.
// ---------------------------------------------------------------------------
__global__ void prep_kernel(const float* __restrict__ x_in,
                            const float* __restrict__ thw,
                            const float* __restrict__ phw,
                            const float* __restrict__ ow) {
    extern __shared__ float sm[];
    float* xs = sm;              // [64][256]
    float* w  = sm + CC * 256;   // [128][64]

    int bt = blockIdx.x, b = bt >> 3, t = bt & 7;
    int p0 = blockIdx.y * 256;
    int tid = threadIdx.x;

    for (int c = 0; c < CC; ++c)
        xs[c * 256 + tid] = x_in[((b * CC + c) * TT + t) * PP + p0 + tid];
    for (int i = tid; i < CC2 * CC; i += 256) {
        w[i]            = thw[t * CC2 * CC + i];
        w[CC2 * CC + i] = phw[t * CC2 * CC + i];
    }
    for (int i = tid; i < CC * CC; i += 256)
        w[2 * CC2 * CC + i] = ow[i];
    __syncthreads();

    int base = bt * PP + p0 + tid;

    float acc[8];
    for (int g = 0; g < 16; ++g) {
        #pragma unroll
        for (int u = 0; u < 8; ++u) acc[u] = 0.f;
        const float* wr = &w[(g * 8) * CC];
        #pragma unroll 8
        for (int c = 0; c < CC; ++c) {
            float xc = xs[c * 256 + tid];
            #pragma unroll
            for (int u = 0; u < 8; ++u)
                acc[u] = fmaf(wr[u * CC + c], xc, acc[u]);
        }
        float4 v0 = make_float4(acc[0], acc[1], acc[2], acc[3]);
        float4 v1 = make_float4(acc[4], acc[5], acc[6], acc[7]);
        int r = g * 8;
        float4* dst;
        if (r < CC2)          dst = (float4*)&g_theta[(size_t)base * CC2 + r];
        else if (r < 2 * CC2) dst = (float4*)&g_phi  [(size_t)base * CC2 + (r - CC2)];
        else                  dst = (float4*)&g_v    [(size_t)base * CC  + (r - 2 * CC2)];
        dst[0] = v0; dst[1] = v1;
    }
}

// ---------------------------------------------------------------------------
// Kernel B: flash attention, fp32 via packed FFMA2 (fma.rn.f32x2).
//  Qd: Q rows duplicated (q,q) per c          [128][68]
//  KP: col-pair layout (K[j][c], K[j+64][c])  [64][68]
//  Vs: plain                                   [128][64]
//  Pd: P duplicated (p,p) per j               [128][260]
// No running max (scores bounded); row sums deferred to epilogue.
// ---------------------------------------------------------------------------
#define QD_S 68
#define KP_S 68
#define PD_S 260

__global__ void __launch_bounds__(512, 1)
flash_kernel(const float* __restrict__ x_in, float* __restrict__ out) {
    extern __shared__ float sm[];
    float* Qd = sm;                    // 128*68
    float* KP = Qd + 128 * QD_S;       // 64*68
    float* Vs = KP + 64 * KP_S;        // 128*64
    float* Pd = Vs + 128 * 64;         // 128*260 (epilogue: O^T [64][132])

    int bt = blockIdx.y, b = bt >> 3, t = bt & 7;
    int q0 = blockIdx.x * 128;
    int tid = threadIdx.x, tx = tid & 31, ty = tid >> 5;
    int base = bt * PP;
    const float scale2 = 0.17677669529663689f * 1.4426950408889634f; // 1/sqrt(32) * log2(e)

    // stage Q duplicated + scaled
    for (int i = tid; i < 1024; i += 512) {
        int r = i >> 3, c4 = (i & 7) << 2;
        float4 q = *(const float4*)&g_theta[(size_t)(base + q0 + r) * CC2 + c4];
        float* d = &Qd[r * QD_S + 2 * c4];
        *(float4*)&d[0] = make_float4(q.x * scale2, q.x * scale2, q.y * scale2, q.y * scale2);
        *(float4*)&d[4] = make_float4(q.z * scale2, q.z * scale2, q.w * scale2, q.w * scale2);
    }

    ull O2[8];
    float lsum[8];
    #pragma unroll
    for (int k = 0; k < 8; ++k) { O2[k] = 0ull; lsum[k] = 0.f; }

    for (int kt = 0; kt < PP / 128; ++kt) {
        int k0 = kt * 128;
        // stage K as col-pairs (j, j+64)
        for (int i = tid; i < 1024; i += 512) {
            int r = i >> 3, c4 = (i & 7) << 2;
            float4 kv = *(const float4*)&g_phi[(size_t)(base + k0 + r) * CC2 + c4];
            float* d = &KP[(r & 63) * KP_S + (r >> 6)];
            d[2 * c4 + 0] = kv.x; d[2 * c4 + 2] = kv.y;
            d[2 * c4 + 4] = kv.z; d[2 * c4 + 6] = kv.w;
        }
        // stage V
        for (int i = tid; i < 2048; i += 512) {
            int r = i >> 4, c4 = (i & 15) << 2;
            *(float4*)&Vs[r * 64 + c4] = *(const float4*)&g_v[(size_t)(base + k0 + r) * CC + c4];
        }
        __syncthreads();

        // S = Q K^T : acc[k][0]=(S[tx],S[tx+64]), acc[k][1]=(S[tx+32],S[tx+96])
        ull acc[8][2];
        #pragma unroll
        for (int k = 0; k < 8; ++k) { acc[k][0] = 0ull; acc[k][1] = 0ull; }

        #pragma unroll 4
        for (int cc = 0; cc < 32; cc += 4) {
            ulonglong2 k0a = *(ulonglong2*)&KP[tx * KP_S + 2 * cc];
            ulonglong2 k0b = *(ulonglong2*)&KP[tx * KP_S + 2 * cc + 4];
            ulonglong2 k1a = *(ulonglong2*)&KP[(tx + 32) * KP_S + 2 * cc];
            ulonglong2 k1b = *(ulonglong2*)&KP[(tx + 32) * KP_S + 2 * cc + 4];
            #pragma unroll
            for (int k = 0; k < 8; ++k) {
                ulonglong2 qa = *(ulonglong2*)&Qd[(ty + 16 * k) * QD_S + 2 * cc];
                ulonglong2 qb = *(ulonglong2*)&Qd[(ty + 16 * k) * QD_S + 2 * cc + 4];
                FMA2(acc[k][0], qa.x, k0a.x);
                FMA2(acc[k][1], qa.x, k1a.x);
                FMA2(acc[k][0], qa.y, k0a.y);
                FMA2(acc[k][1], qa.y, k1a.y);
                FMA2(acc[k][0], qb.x, k0b.x);
                FMA2(acc[k][1], qb.x, k1b.x);
                FMA2(acc[k][0], qb.y, k0b.y);
                FMA2(acc[k][1], qb.y, k1b.y);
            }
        }

        // exp (base-2, no max subtraction) + duplicated P store + deferred sums
        #pragma unroll
        for (int k = 0; k < 8; ++k) {
            int row = ty + 16 * k;
            float p0 = ex2(f2lo(acc[k][0]));
            float p1 = ex2(f2hi(acc[k][0]));
            float p2 = ex2(f2lo(acc[k][1]));
            float p3 = ex2(f2hi(acc[k][1]));
            lsum[k] += (p0 + p2) + (p1 + p3);
            float* pr = &Pd[row * PD_S];
            *(float2*)&pr[2 * tx      ] = make_float2(p0, p0);   // col tx
            *(float2*)&pr[2 * tx + 64 ] = make_float2(p2, p2);   // col tx+32
            *(float2*)&pr[2 * tx + 128] = make_float2(p1, p1);   // col tx+64
            *(float2*)&pr[2 * tx + 192] = make_float2(p3, p3);   // col tx+96
        }
        __syncthreads();

        // O += P V : O2[k] = (O[row][2tx], O[row][2tx+1])
        #pragma unroll 4
        for (int j = 0; j < 128; j += 2) {
            ull v0 = *(ull*)&Vs[ j      * 64 + 2 * tx];
            ull v1 = *(ull*)&Vs[(j + 1) * 64 + 2 * tx];
            #pragma unroll
            for (int k = 0; k < 8; ++k) {
                ulonglong2 p2 = *(ulonglong2*)&Pd[(ty + 16 * k) * PD_S + 2 * j];
                FMA2(O2[k], p2.x, v0);
                FMA2(O2[k], p2.y, v1);
            }
        }
        __syncthreads();
    }

    // final row-sum reduction (once) and normalize
    float linv[8];
    #pragma unroll
    for (int k = 0; k < 8; ++k) {
        float s = lsum[k];
        #pragma unroll
        for (int off = 16; off > 0; off >>= 1)
            s += __shfl_xor_sync(0xffffffffu, s, off);
        linv[k] = 1.f / s;
    }
    // transpose O via smem (reuse Pd)
    #pragma unroll
    for (int k = 0; k < 8; ++k) {
        int r = ty + 16 * k;
        Pd[(2 * tx    ) * 132 + r] = f2lo(O2[k]) * linv[k];
        Pd[(2 * tx + 1) * 132 + r] = f2hi(O2[k]) * linv[k];
    }
    __syncthreads();

    // out[b, o, t, p] = O^T[o][p-q0] + x_in[b, o, t, p]
    for (int i = tid; i < 2048; i += 512) {
        int o = i >> 5, r4 = (i & 31) << 2;
        float4 ov = *(float4*)&Pd[o * 132 + r4];
        int g = ((b * CC + o) * TT + t) * PP + q0 + r4;
        float4 xr = *(const float4*)&x_in[g];
        ov.x += xr.x; ov.y += xr.y; ov.z += xr.z; ov.w += xr.w;
        *(float4*)&out[g] = ov;
    }
}

// ---------------------------------------------------------------------------

extern "C" void kernel_launch(void* const* d_in, const int* in_sizes, int n_in,
                              void* d_out, int out_size) {
    const float* x_in = (const float*)d_in[0];
    const float* thw  = (const float*)d_in[1];
    const float* phw  = (const float*)d_in[2];
    const float* ow   = (const float*)d_in[3];
    float* out = (float*)d_out;

    const int prep_smem  = (CC * 256 + 128 * CC) * 4;                              // 98304 B
    const int flash_smem = (128 * QD_S + 64 * KP_S + 128 * 64 + 128 * PD_S) * 4;   // 218112 B

    cudaFuncSetAttribute(prep_kernel,  cudaFuncAttributeMaxDynamicSharedMemorySize, prep_smem);
    cudaFuncSetAttribute(flash_kernel, cudaFuncAttributeMaxDynamicSharedMemorySize, flash_smem);

    prep_kernel<<<dim3(NBT, PP / 256), 256, prep_smem>>>(x_in, thw, phw, ow);
    flash_kernel<<<dim3(PP / 128, NBT), 512, flash_smem>>>(x_in, out);
}

// round 6
// speedup vs baseline: 6.1212x; 6.1212x over previous
#include <cuda_runtime.h>
#include <cuda_bf16.h>
#include <cstdint>

#define CC    64
#define CC2   32
#define TT    8
#define PP    2304
#define NBT   16
#define NTILE 18

typedef unsigned int u32;
typedef unsigned long long u64;

__device__ __nv_bfloat16 g_q [NBT * PP * CC2];   // theta * scale * log2e, [bt][p][32]
__device__ __nv_bfloat16 g_k [NBT * PP * CC2];   // phi,                  [bt][p][32]
__device__ __nv_bfloat16 g_vt[NBT * CC * PP];    // (out_w @ x)^T,        [bt][o][p]

__device__ __forceinline__ float ex2(float x){ float y; asm("ex2.approx.ftz.f32 %0, %1;":"=f"(y):"f"(x)); return y; }
__device__ __forceinline__ u32 smem_u32(const void* p){
    u32 a; asm("{ .reg .u64 t; cvta.to.shared.u64 t, %1; cvt.u32.u64 %0, t; }":"=r"(a):"l"(p)); return a;
}
__device__ __forceinline__ u32 pack_bf16x2(float lo, float hi){
    u32 r; asm("cvt.rn.satfinite.bf16x2.f32 %0, %1, %2;" : "=r"(r) : "f"(hi), "f"(lo)); return r;
}

#define LDSM4(r, a) \
    asm volatile("ldmatrix.sync.aligned.m8n8.x4.shared.b16 {%0,%1,%2,%3}, [%4];" \
        : "=r"((r)[0]),"=r"((r)[1]),"=r"((r)[2]),"=r"((r)[3]) : "r"(a))

#define MMA16816(d, a0, a1, a2, a3, b0, b1) \
    asm volatile("mma.sync.aligned.m16n8k16.row.col.f32.bf16.bf16.f32 " \
        "{%0,%1,%2,%3}, {%4,%5,%6,%7}, {%8,%9}, {%0,%1,%2,%3};" \
        : "+f"((d)[0]),"+f"((d)[1]),"+f"((d)[2]),"+f"((d)[3]) \
        : "r"(a0),"r"(a1),"r"(a2),"r"(a3), "r"(b0),"r"(b1))

#define CP16(dst, src) \
    asm volatile("cp.async.cg.shared.global [%0], [%1], 16;" :: "r"(dst), "l"(src))
#define CP_COMMIT() asm volatile("cp.async.commit_group;" ::: "memory")
#define CP_WAIT0()  asm volatile("cp.async.wait_group 0;" ::: "memory")

// ---------------------------------------------------------------------------
// Kernel A: per-(b,t) projections, fp32 compute, bf16 stores. out_w folded
// into V; V stored transposed [o][p] (keys contiguous, for the PV B-operand).
// ---------------------------------------------------------------------------
__global__ void prep_kernel(const float* __restrict__ x_in,
                            const float* __restrict__ thw,
                            const float* __restrict__ phw,
                            const float* __restrict__ ow) {
    extern __shared__ float sm[];
    float* xs = sm;              // [64][256]
    float* w  = sm + CC * 256;   // [128][64]

    int bt = blockIdx.x, b = bt >> 3, t = bt & 7;
    int p0 = blockIdx.y * 256;
    int tid = threadIdx.x;

    for (int c = 0; c < CC; ++c)
        xs[c * 256 + tid] = x_in[((b * CC + c) * TT + t) * PP + p0 + tid];
    for (int i = tid; i < CC2 * CC; i += 256) {
        w[i]            = thw[t * CC2 * CC + i];
        w[CC2 * CC + i] = phw[t * CC2 * CC + i];
    }
    for (int i = tid; i < CC * CC; i += 256)
        w[2 * CC2 * CC + i] = ow[i];
    __syncthreads();

    const int p = p0 + tid;
    const size_t base = (size_t)bt * PP + p;
    const float s2 = 0.17677669529663689f * 1.4426950408889634f;  // 1/sqrt(32)*log2(e)

    float acc[8];
    for (int g = 0; g < 16; ++g) {
        #pragma unroll
        for (int u = 0; u < 8; ++u) acc[u] = 0.f;
        const float* wr = &w[(g * 8) * CC];
        #pragma unroll 8
        for (int c = 0; c < CC; ++c) {
            float xc = xs[c * 256 + tid];
            #pragma unroll
            for (int u = 0; u < 8; ++u)
                acc[u] = fmaf(wr[u * CC + c], xc, acc[u]);
        }
        int r = g * 8;
        if (r < CC2) {
            uint4 h;
            h.x = pack_bf16x2(acc[0]*s2, acc[1]*s2);
            h.y = pack_bf16x2(acc[2]*s2, acc[3]*s2);
            h.z = pack_bf16x2(acc[4]*s2, acc[5]*s2);
            h.w = pack_bf16x2(acc[6]*s2, acc[7]*s2);
            *(uint4*)&g_q[base * CC2 + r] = h;
        } else if (r < 2 * CC2) {
            uint4 h;
            h.x = pack_bf16x2(acc[0], acc[1]);
            h.y = pack_bf16x2(acc[2], acc[3]);
            h.z = pack_bf16x2(acc[4], acc[5]);
            h.w = pack_bf16x2(acc[6], acc[7]);
            *(uint4*)&g_k[base * CC2 + (r - CC2)] = h;
        } else {
            #pragma unroll
            for (int u = 0; u < 8; ++u)
                g_vt[((size_t)(bt * CC + (r - 2 * CC2) + u)) * PP + p] = __float2bfloat16(acc[u]);
        }
    }
}

// ---------------------------------------------------------------------------
// Kernel B: flash attention via mma.sync (HMMA bf16), 256 threads, grid (18,16).
// smem (bytes): Q[128][40bf16] @0 (10240) | K0 @10240 | K1 @20480 (each 128x40)
//               V0 @30720 | V1 @48128 (each 64 rows x 136 bf16 = 17408)  total 65536
// Epilogue reuses bytes 10240.. as O^T [64][132] f32.
// ---------------------------------------------------------------------------
#define QK_STB  80     // K/Q row stride bytes (40 bf16)
#define VT_STB  272    // Vt row stride bytes (136 bf16)
#define SMB_Q   0
#define SMB_K0  10240
#define SMB_K1  20480
#define SMB_V0  30720
#define SMB_V1  48128
#define SMB_END 65536
#define SMB_OT  10240
#define OT_S    132

__global__ void __launch_bounds__(256)
flash_kernel(const float* __restrict__ x_in, float* __restrict__ out) {
    extern __shared__ char smem[];
    const u32 sb  = smem_u32(smem);
    const int tid  = threadIdx.x;
    const int w    = tid >> 5, lane = tid & 31;
    const int g    = lane >> 2, tq = lane & 3;       // quad row / quad thread
    const int lm   = lane >> 3, lr = lane & 7;       // ldmatrix: matrix id / row
    const int bt   = blockIdx.y, b = bt >> 3, t = bt & 7;
    const int q0   = blockIdx.x * 128;

    // global src bases for the cp.async loaders
    const int krow = tid >> 1, khalf = tid & 1;          // K/Q: 2 threads per row
    const int vo   = tid >> 2, vqt  = tid & 3;           // V: 4 threads per o-row
    const __nv_bfloat16* gq = &g_q[((size_t)bt * PP + q0 + krow) * CC2 + khalf * 16];
    const __nv_bfloat16* gk = &g_k[((size_t)bt * PP + krow) * CC2 + khalf * 16];
    const __nv_bfloat16* gv = &g_vt[((size_t)(bt * CC + vo)) * PP + vqt * 32];
    const u32 dq = sb + SMB_Q  + krow * QK_STB + khalf * 32;
    const u32 dk0 = sb + SMB_K0 + krow * QK_STB + khalf * 32;
    const u32 dk1 = sb + SMB_K1 + krow * QK_STB + khalf * 32;
    const u32 dv0 = sb + SMB_V0 + vo * VT_STB + vqt * 64;
    const u32 dv1 = sb + SMB_V1 + vo * VT_STB + vqt * 64;

    // stage Q + K0 + V0
    CP16(dq,      gq);      CP16(dq + 16,  gq + 8);
    CP16(dk0,     gk);      CP16(dk0 + 16, gk + 8);
    CP16(dv0,      gv);      CP16(dv0 + 16, gv + 8);
    CP16(dv0 + 32, gv + 16); CP16(dv0 + 48, gv + 24);
    CP_COMMIT(); CP_WAIT0();
    __syncthreads();

    // Q A-fragments (held in registers for the whole kernel)
    u32 aq[2][4];
    {
        const u32 qb = sb + SMB_Q + (w * 16 + (lm & 1) * 8 + lr) * QK_STB + (lm >> 1) * 16;
        LDSM4(aq[0], qb);
        LDSM4(aq[1], qb + 32);
    }

    float o[8][4];
    #pragma unroll
    for (int i = 0; i < 8; ++i)
        #pragma unroll
        for (int j = 0; j < 4; ++j) o[i][j] = 0.f;
    float lsum_lo = 0.f, lsum_hi = 0.f;

    const u32 kldb[2] = { sb + SMB_K0 + lr * QK_STB + lm * 16,
                          sb + SMB_K1 + lr * QK_STB + lm * 16 };
    const u32 vldb[2] = { sb + SMB_V0 + lr * VT_STB + lm * 16,
                          sb + SMB_V1 + lr * VT_STB + lm * 16 };

    for (int kt = 0; kt < NTILE; ++kt) {
        const int cb = kt & 1, nb = cb ^ 1;
        const bool more = (kt + 1 < NTILE);

        // prefetch next K/V tile into the other buffer (async, no regs)
        if (more) {
            const __nv_bfloat16* nk = gk + (size_t)(kt + 1) * 128 * CC2;
            const __nv_bfloat16* nv = gv + (kt + 1) * 128;
            const u32 tdk = nb ? dk1 : dk0;
            const u32 tdv = nb ? dv1 : dv0;
            CP16(tdk,      nk);      CP16(tdk + 16, nk + 8);
            CP16(tdv,      nv);      CP16(tdv + 16, nv + 8);
            CP16(tdv + 32, nv + 16); CP16(tdv + 48, nv + 24);
            CP_COMMIT();
        }

        // ---- S = Q K^T : 16 n-frags of 8 keys ----
        float s[16][4];
        #pragma unroll
        for (int nf = 0; nf < 16; ++nf) {
            u32 kb[4];
            LDSM4(kb, kldb[cb] + nf * 8 * QK_STB);
            s[nf][0] = 0.f; s[nf][1] = 0.f; s[nf][2] = 0.f; s[nf][3] = 0.f;
            MMA16816(s[nf], aq[0][0], aq[0][1], aq[0][2], aq[0][3], kb[0], kb[1]);
            MMA16816(s[nf], aq[1][0], aq[1][1], aq[1][2], aq[1][3], kb[2], kb[3]);
        }

        // ---- softmax (no max subtraction; scores bounded) + pack to bf16 ----
        u32 pf[16][2];
        #pragma unroll
        for (int nf = 0; nf < 16; ++nf) {
            float e0 = ex2(s[nf][0]), e1 = ex2(s[nf][1]);
            float e2 = ex2(s[nf][2]), e3 = ex2(s[nf][3]);
            lsum_lo += e0 + e1;
            lsum_hi += e2 + e3;
            pf[nf][0] = pack_bf16x2(e0, e1);
            pf[nf][1] = pack_bf16x2(e2, e3);
        }

        // ---- O += P V : 8 o-groups x 4 key-pair steps ----
        #pragma unroll
        for (int nf2 = 0; nf2 < 8; ++nf2) {
            #pragma unroll
            for (int kp = 0; kp < 4; ++kp) {
                u32 vb[4];
                LDSM4(vb, vldb[cb] + nf2 * 8 * VT_STB + kp * 64);
                MMA16816(o[nf2], pf[4*kp][0], pf[4*kp][1], pf[4*kp+1][0], pf[4*kp+1][1], vb[0], vb[1]);
                MMA16816(o[nf2], pf[4*kp+2][0], pf[4*kp+2][1], pf[4*kp+3][0], pf[4*kp+3][1], vb[2], vb[3]);
            }
        }

        CP_WAIT0();
        __syncthreads();
    }

    // ---- reduce row sums across quad, normalize, transpose via smem ----
    lsum_lo += __shfl_xor_sync(0xffffffffu, lsum_lo, 1);
    lsum_lo += __shfl_xor_sync(0xffffffffu, lsum_lo, 2);
    lsum_hi += __shfl_xor_sync(0xffffffffu, lsum_hi, 1);
    lsum_hi += __shfl_xor_sync(0xffffffffu, lsum_hi, 2);
    const float inv_lo = 1.f / lsum_lo, inv_hi = 1.f / lsum_hi;

    float* ot = (float*)(smem + SMB_OT);
    const int prow = w * 16 + g;
    #pragma unroll
    for (int nf2 = 0; nf2 < 8; ++nf2) {
        int oc = nf2 * 8 + 2 * tq;
        ot[(oc    ) * OT_S + prow    ] = o[nf2][0] * inv_lo;
        ot[(oc + 1) * OT_S + prow    ] = o[nf2][1] * inv_lo;
        ot[(oc    ) * OT_S + prow + 8] = o[nf2][2] * inv_hi;
        ot[(oc + 1) * OT_S + prow + 8] = o[nf2][3] * inv_hi;
    }
    __syncthreads();

    // out[b, o, t, q0 + p] = O^T + residual  (coalesced float4)
    {
        const int oc = tid >> 2, qt = tid & 3;
        const size_t gb = ((size_t)(b * CC + oc) * TT + t) * PP + q0 + qt * 32;
        const float* src = &ot[oc * OT_S + qt * 32];
        #pragma unroll
        for (int j = 0; j < 8; ++j) {
            float4 v = *(const float4*)&src[4 * j];
            float4 x = *(const float4*)&x_in[gb + 4 * j];
            v.x += x.x; v.y += x.y; v.z += x.z; v.w += x.w;
            *(float4*)&out[gb + 4 * j] = v;
        }
    }
}

// ---------------------------------------------------------------------------

extern "C" void kernel_launch(void* const* d_in, const int* in_sizes, int n_in,
                              void* d_out, int out_size) {
    const float* x_in = (const float*)d_in[0];
    const float* thw  = (const float*)d_in[1];
    const float* phw  = (const float*)d_in[2];
    const float* ow   = (const float*)d_in[3];
    float* out = (float*)d_out;

    const int prep_smem  = (CC * 256 + 128 * CC) * 4;  // 98304 B
    const int flash_smem = SMB_END;                    // 65536 B

    cudaFuncSetAttribute(prep_kernel,  cudaFuncAttributeMaxDynamicSharedMemorySize, prep_smem);
    cudaFuncSetAttribute(flash_kernel, cudaFuncAttributeMaxDynamicSharedMemorySize, flash_smem);

    prep_kernel<<<dim3(NBT, PP / 256), 256, prep_smem>>>(x_in, thw, phw, ow);
    flash_kernel<<<dim3(PP / 128, NBT), 256, flash_smem>>>(x_in, out);
}

// round 8
// speedup vs baseline: 6.6723x; 1.0900x over previous
#include <cuda_runtime.h>
#include <cuda_fp16.h>
#include <cstdint>

#define CC    64
#define CC2   32
#define TT    8
#define PP    2304
#define NBT   16
#define NTILE 18
#define VROWS 72

typedef unsigned int u32;

__device__ __half g_q [NBT * PP * CC2];      // theta * scale * log2e, [bt][p][32]
__device__ __half g_k [NBT * PP * CC2];      // phi,                  [bt][p][32]
__device__ __half g_vt[NBT * VROWS * PP];    // (out_w @ x)^T + ones row, [bt][o][p]

__device__ __forceinline__ u32 smem_u32(const void* p){
    u32 a; asm("{ .reg .u64 t; cvta.to.shared.u64 t, %1; cvt.u32.u64 %0, t; }":"=r"(a):"l"(p)); return a;
}

#define LDSM4(r, a) \
    asm volatile("ldmatrix.sync.aligned.m8n8.x4.shared.b16 {%0,%1,%2,%3}, [%4];" \
        : "=r"((r)[0]),"=r"((r)[1]),"=r"((r)[2]),"=r"((r)[3]) : "r"(a))

#define MMAF16(d, a0, a1, a2, a3, b0, b1) \
    asm volatile("mma.sync.aligned.m16n8k16.row.col.f32.f16.f16.f32 " \
        "{%0,%1,%2,%3}, {%4,%5,%6,%7}, {%8,%9}, {%0,%1,%2,%3};" \
        : "+f"((d)[0]),"+f"((d)[1]),"+f"((d)[2]),"+f"((d)[3]) \
        : "r"(a0),"r"(a1),"r"(a2),"r"(a3), "r"(b0),"r"(b1))

#define CP16(dst, src) \
    asm volatile("cp.async.cg.shared.global [%0], [%1], 16;" :: "r"(dst), "l"(src))
#define CP_COMMIT() asm volatile("cp.async.commit_group;" ::: "memory")
#define CP_WAIT0()  asm volatile("cp.async.wait_group 0;" ::: "memory")

__device__ __forceinline__ u32 h2_u32(__half2 h){ return *(u32*)&h; }

// ---------------------------------------------------------------------------
// Kernel A: per-(b,t) projections, fp32 compute, fp16 stores. out_w folded
// into V; V stored transposed [o][p] with rows 64..71 = {ones, zeros} for the
// row-sum column trick. grid (16, 18), block 256, 2 threads per point.
// ---------------------------------------------------------------------------
__global__ void __launch_bounds__(256)
prep_kernel(const float* __restrict__ x_in,
            const float* __restrict__ thw,
            const float* __restrict__ phw,
            const float* __restrict__ ow) {
    extern __shared__ float sm[];
    float* xs = sm;              // [64][128]
    float* w  = sm + CC * 128;   // [128][64]: 0-31 theta, 32-63 phi, 64-127 out_w

    const int bt = blockIdx.x, b = bt >> 3, t = bt & 7;
    const int p0 = blockIdx.y * 128;
    const int tid = threadIdx.x;

    for (int i = tid; i < CC * 128; i += 256) {
        int c = i >> 7, pl = i & 127;
        xs[i] = x_in[((b * CC + c) * TT + t) * PP + p0 + pl];
    }
    for (int i = tid; i < CC2 * CC; i += 256) {
        w[i]            = thw[t * CC2 * CC + i];
        w[CC2 * CC + i] = phw[t * CC2 * CC + i];
    }
    for (int i = tid; i < CC * CC; i += 256)
        w[2 * CC2 * CC + i] = ow[i];
    __syncthreads();

    const int pl = tid & 127, h = tid >> 7;
    const int p  = p0 + pl;
    const size_t qkbase = ((size_t)bt * PP + p) * CC2;
    const float s2 = 0.17677669529663689f * 1.4426950408889634f;  // 1/sqrt(32)*log2(e)

    float acc[8];
    for (int g = 0; g < 8; ++g) {
        #pragma unroll
        for (int u = 0; u < 8; ++u) acc[u] = 0.f;
        const float* wr = &w[(h * 64 + g * 8) * CC];
        #pragma unroll 8
        for (int c = 0; c < CC; ++c) {
            float xc = xs[c * 128 + pl];
            #pragma unroll
            for (int u = 0; u < 8; ++u)
                acc[u] = fmaf(wr[u * CC + c], xc, acc[u]);
        }
        if (h == 0) {
            // outputs 0..63: theta (g<4) -> q scaled, phi (g>=4) -> k
            uint4 hv;
            if (g < 4) {
                hv.x = h2_u32(__floats2half2_rn(acc[0]*s2, acc[1]*s2));
                hv.y = h2_u32(__floats2half2_rn(acc[2]*s2, acc[3]*s2));
                hv.z = h2_u32(__floats2half2_rn(acc[4]*s2, acc[5]*s2));
                hv.w = h2_u32(__floats2half2_rn(acc[6]*s2, acc[7]*s2));
                *(uint4*)&g_q[qkbase + g * 8] = hv;
            } else {
                hv.x = h2_u32(__floats2half2_rn(acc[0], acc[1]));
                hv.y = h2_u32(__floats2half2_rn(acc[2], acc[3]));
                hv.z = h2_u32(__floats2half2_rn(acc[4], acc[5]));
                hv.w = h2_u32(__floats2half2_rn(acc[6], acc[7]));
                *(uint4*)&g_k[qkbase + (g - 4) * 8] = hv;
            }
        } else {
            // outputs 64..127: v rows (o = g*8+u)
            #pragma unroll
            for (int u = 0; u < 8; ++u)
                g_vt[((size_t)bt * VROWS + g * 8 + u) * PP + p] = __float2half(acc[u]);
        }
    }
    if (h == 1) {
        g_vt[((size_t)bt * VROWS + 64) * PP + p] = __float2half(1.0f);
        #pragma unroll
        for (int r = 1; r < 8; ++r)
            g_vt[((size_t)bt * VROWS + 64 + r) * PP + p] = __float2half(0.0f);
    }
}

// ---------------------------------------------------------------------------
// Kernel B: flash attention via mma.sync fp16, 256 threads, grid (18,16).
// smem: Q @0 (128x80B) | K0 @10240 | K1 @20480 | V0 @30720 | V1 @50304
//       (V tiles: 72 rows x 272B). Epilogue reuses @0 as O^T [64][132] f32.
// Row sums come for free from V's ones-column (o-col 64).
// ---------------------------------------------------------------------------
#define QK_STB  80
#define VT_STB  272
#define SMB_Q   0
#define SMB_K0  10240
#define SMB_K1  20480
#define SMB_V0  30720
#define SMB_V1  50304
#define SMB_END 69888
#define OT_S    132

__global__ void __launch_bounds__(256)
flash_kernel(const float* __restrict__ x_in, float* __restrict__ out) {
    extern __shared__ char smem[];
    const u32 sb  = smem_u32(smem);
    const int tid  = threadIdx.x;
    const int w    = tid >> 5, lane = tid & 31;
    const int g    = lane >> 2, tq = lane & 3;
    const int lm   = lane >> 3, lr = lane & 7;
    const int bt   = blockIdx.y, b = bt >> 3, t = bt & 7;
    const int q0   = blockIdx.x * 128;

    const __half* gqb = &g_q[(size_t)bt * PP * CC2];
    const __half* gkb = &g_k[(size_t)bt * PP * CC2];
    const __half* gvb = &g_vt[(size_t)bt * VROWS * PP];

    // ---- initial stage: Q tile + K0 + V0 ----
    {
        // Q/K: 128 rows x 64B = 512 16B-chunks
        #pragma unroll
        for (int j = 0; j < 2; ++j) {
            int idx = tid + j * 256;
            int row = idx >> 2, col = idx & 3;
            CP16(sb + SMB_Q  + row * QK_STB + col * 16, gqb + (size_t)(q0 + row) * CC2 + col * 8);
            CP16(sb + SMB_K0 + row * QK_STB + col * 16, gkb + (size_t)row * CC2 + col * 8);
        }
        // V: 72 rows x 256B = 1152 16B-chunks
        #pragma unroll
        for (int j = 0; j < 5; ++j) {
            int idx = tid + j * 256;
            if (idx < 1152) {
                int row = idx >> 4, col = idx & 15;
                CP16(sb + SMB_V0 + row * VT_STB + col * 16, gvb + (size_t)row * PP + col * 8);
            }
        }
    }
    CP_COMMIT(); CP_WAIT0();
    __syncthreads();

    // Q A-fragments (registers, whole kernel)
    u32 aq[2][4];
    {
        const u32 qb = sb + SMB_Q + (w * 16 + (lm & 1) * 8 + lr) * QK_STB + (lm >> 1) * 16;
        LDSM4(aq[0], qb);
        LDSM4(aq[1], qb + 32);
    }

    float o[9][4];
    #pragma unroll
    for (int i = 0; i < 9; ++i)
        #pragma unroll
        for (int j = 0; j < 4; ++j) o[i][j] = 0.f;

    const u32 kldb[2] = { sb + SMB_K0 + lr * QK_STB + lm * 16,
                          sb + SMB_K1 + lr * QK_STB + lm * 16 };
    const u32 vldb[2] = { sb + SMB_V0 + lr * VT_STB + lm * 16,
                          sb + SMB_V1 + lr * VT_STB + lm * 16 };

    for (int kt = 0; kt < NTILE; ++kt) {
        const int cb = kt & 1, nb = cb ^ 1;
        const bool more = (kt + 1 < NTILE);

        // prefetch next K/V tile into the other buffer
        if (more) {
            const int k0 = (kt + 1) * 128;
            const u32 kdst = sb + (nb ? SMB_K1 : SMB_K0);
            const u32 vdst = sb + (nb ? SMB_V1 : SMB_V0);
            #pragma unroll
            for (int j = 0; j < 2; ++j) {
                int idx = tid + j * 256;
                int row = idx >> 2, col = idx & 3;
                CP16(kdst + row * QK_STB + col * 16, gkb + (size_t)(k0 + row) * CC2 + col * 8);
            }
            #pragma unroll
            for (int j = 0; j < 5; ++j) {
                int idx = tid + j * 256;
                if (idx < 1152) {
                    int row = idx >> 4, col = idx & 15;
                    CP16(vdst + row * VT_STB + col * 16, gvb + (size_t)row * PP + k0 + col * 8);
                }
            }
            CP_COMMIT();
        }

        // ---- S = Q K^T : 16 n-frags of 8 keys ----
        float s[16][4];
        #pragma unroll
        for (int nf = 0; nf < 16; ++nf) {
            u32 kb[4];
            LDSM4(kb, kldb[cb] + nf * 8 * QK_STB);
            s[nf][0] = 0.f; s[nf][1] = 0.f; s[nf][2] = 0.f; s[nf][3] = 0.f;
            MMAF16(s[nf], aq[0][0], aq[0][1], aq[0][2], aq[0][3], kb[0], kb[1]);
            MMAF16(s[nf], aq[1][0], aq[1][1], aq[1][2], aq[1][3], kb[2], kb[3]);
        }

        // ---- softmax: pack f32x2 -> f16x2, ex2 in f16x2 (no max; bounded) ----
        u32 pf[16][2];
        #pragma unroll
        for (int nf = 0; nf < 16; ++nf) {
            __half2 h0 = h2exp2(__floats2half2_rn(s[nf][0], s[nf][1]));
            __half2 h1 = h2exp2(__floats2half2_rn(s[nf][2], s[nf][3]));
            pf[nf][0] = h2_u32(h0);
            pf[nf][1] = h2_u32(h1);
        }

        // ---- O += P V : 9 o-groups (last = ones column -> row sums) ----
        #pragma unroll
        for (int nf2 = 0; nf2 < 9; ++nf2) {
            #pragma unroll
            for (int kp = 0; kp < 4; ++kp) {
                u32 vb[4];
                LDSM4(vb, vldb[cb] + nf2 * 8 * VT_STB + kp * 64);
                MMAF16(o[nf2], pf[4*kp][0], pf[4*kp][1], pf[4*kp+1][0], pf[4*kp+1][1], vb[0], vb[1]);
                MMAF16(o[nf2], pf[4*kp+2][0], pf[4*kp+2][1], pf[4*kp+3][0], pf[4*kp+3][1], vb[2], vb[3]);
            }
        }

        CP_WAIT0();
        __syncthreads();
    }

    // ---- row sums from ones-column (col 64 lives in tq==0 lanes) ----
    const int qlead = lane & 28;
    const float inv_lo = 1.f / __shfl_sync(0xffffffffu, o[8][0], qlead);
    const float inv_hi = 1.f / __shfl_sync(0xffffffffu, o[8][2], qlead);

    float* ot = (float*)smem;
    const int prow = w * 16 + g;
    #pragma unroll
    for (int nf2 = 0; nf2 < 8; ++nf2) {
        int oc = nf2 * 8 + 2 * tq;
        ot[(oc    ) * OT_S + prow    ] = o[nf2][0] * inv_lo;
        ot[(oc + 1) * OT_S + prow    ] = o[nf2][1] * inv_lo;
        ot[(oc    ) * OT_S + prow + 8] = o[nf2][2] * inv_hi;
        ot[(oc + 1) * OT_S + prow + 8] = o[nf2][3] * inv_hi;
    }
    __syncthreads();

    // out[b, o, t, q0 + p] = O^T + residual (coalesced float4)
    {
        const int oc = tid >> 2, qt = tid & 3;
        const size_t gb = ((size_t)(b * CC + oc) * TT + t) * PP + q0 + qt * 32;
        const float* src = &ot[oc * OT_S + qt * 32];
        #pragma unroll
        for (int j = 0; j < 8; ++j) {
            float4 v = *(const float4*)&src[4 * j];
            float4 x = *(const float4*)&x_in[gb + 4 * j];
            v.x += x.x; v.y += x.y; v.z += x.z; v.w += x.w;
            *(float4*)&out[gb + 4 * j] = v;
        }
    }
}

// ---------------------------------------------------------------------------

extern "C" void kernel_launch(void* const* d_in, const int* in_sizes, int n_in,
                              void* d_out, int out_size) {
    const float* x_in = (const float*)d_in[0];
    const float* thw  = (const float*)d_in[1];
    const float* phw  = (const float*)d_in[2];
    const float* ow   = (const float*)d_in[3];
    float* out = (float*)d_out;

    const int prep_smem  = (CC * 128 + 128 * CC) * 4;  // 65536 B
    const int flash_smem = SMB_END;                    // 69888 B

    cudaFuncSetAttribute(prep_kernel,  cudaFuncAttributeMaxDynamicSharedMemorySize, prep_smem);
    cudaFuncSetAttribute(flash_kernel, cudaFuncAttributeMaxDynamicSharedMemorySize, flash_smem);

    prep_kernel<<<dim3(NBT, PP / 128), 256, prep_smem>>>(x_in, thw, phw, ow);
    flash_kernel<<<dim3(PP / 128, NBT), 256, flash_smem>>>(x_in, out);
}

// round 9
// speedup vs baseline: 7.5223x; 1.1274x over previous
#include <cuda_runtime.h>
#include <cuda_fp16.h>
#include <cstdint>

#define CC    64
#define CC2   32
#define TT    8
#define PP    2304
#define NBT   16
#define NTILE 18
#define VROWS 72

typedef unsigned int u32;

__device__ __half g_q [NBT * PP * CC2];      // theta * scale * log2e, [bt][p][32]
__device__ __half g_k [NBT * PP * CC2];      // phi,                  [bt][p][32]
__device__ __half g_vt[NBT * VROWS * PP];    // (out_w @ x)^T + ones row, [bt][o][p]

__device__ __forceinline__ u32 smem_u32(const void* p){
    u32 a; asm("{ .reg .u64 t; cvta.to.shared.u64 t, %1; cvt.u32.u64 %0, t; }":"=r"(a):"l"(p)); return a;
}

#define LDSM4(r, a) \
    asm volatile("ldmatrix.sync.aligned.m8n8.x4.shared.b16 {%0,%1,%2,%3}, [%4];" \
        : "=r"((r)[0]),"=r"((r)[1]),"=r"((r)[2]),"=r"((r)[3]) : "r"(a))

#define MMAF16(d, a0, a1, a2, a3, b0, b1) \
    asm volatile("mma.sync.aligned.m16n8k16.row.col.f32.f16.f16.f32 " \
        "{%0,%1,%2,%3}, {%4,%5,%6,%7}, {%8,%9}, {%0,%1,%2,%3};" \
        : "+f"((d)[0]),"+f"((d)[1]),"+f"((d)[2]),"+f"((d)[3]) \
        : "r"(a0),"r"(a1),"r"(a2),"r"(a3), "r"(b0),"r"(b1))

// f16-accumulate variant: D/C are 2x b32 (f16x2); layout == A-fragment layout.
#define MMAF16H(d, a0, a1, a2, a3, b0, b1) \
    asm volatile("mma.sync.aligned.m16n8k16.row.col.f16.f16.f16.f16 " \
        "{%0,%1}, {%2,%3,%4,%5}, {%6,%7}, {%0,%1};" \
        : "+r"((d)[0]),"+r"((d)[1]) \
        : "r"(a0),"r"(a1),"r"(a2),"r"(a3), "r"(b0),"r"(b1))

#define CP16(dst, src) \
    asm volatile("cp.async.cg.shared.global [%0], [%1], 16;" :: "r"(dst), "l"(src))
#define CP_COMMIT() asm volatile("cp.async.commit_group;" ::: "memory")
#define CP_WAIT0()  asm volatile("cp.async.wait_group 0;" ::: "memory")

__device__ __forceinline__ u32 h2_u32(__half2 h){ return *(u32*)&h; }

// ---------------------------------------------------------------------------
// Kernel A: per-(b,t) projections, outer-product register tiling (8x8 per
// thread), W transposed in smem so both operands stream as float4 LDS.
// grid (16, 18), block 256. out_w folded into V; V transposed [o][p] with
// ones row at o=64 (row-sum trick).
// ---------------------------------------------------------------------------
#define XS_S 132
__global__ void __launch_bounds__(256)
prep_kernel(const float* __restrict__ x_in,
            const float* __restrict__ thw,
            const float* __restrict__ phw,
            const float* __restrict__ ow) {
    extern __shared__ float sm[];
    float* xs = sm;               // [64][132] : x[c][p_local]
    float* wt = sm + CC * XS_S;   // [64][132] : W^T[c][r], r: 0-31 th, 32-63 ph, 64-127 ow

    const int bt = blockIdx.x, b = bt >> 3, t = bt & 7;
    const int p0g = blockIdx.y * 128;
    const int tid = threadIdx.x;

    for (int i = tid; i < CC * 128; i += 256) {
        int c = i >> 7, pl = i & 127;
        xs[c * XS_S + pl] = x_in[((b * CC + c) * TT + t) * PP + p0g + pl];
    }
    for (int i = tid; i < CC2 * CC; i += 256) {
        int o = i >> 6, c = i & 63;
        wt[c * XS_S + o]      = thw[t * CC2 * CC + i];
        wt[c * XS_S + 32 + o] = phw[t * CC2 * CC + i];
    }
    for (int i = tid; i < CC * CC; i += 256) {
        int o = i >> 6, c = i & 63;
        wt[c * XS_S + 64 + o] = ow[i];
    }
    __syncthreads();

    const int r0 = (tid >> 4) << 3;      // output-row group (0..120)
    const int p0 = (tid & 15) << 3;      // point group (0..120)

    float acc[8][8];
    #pragma unroll
    for (int u = 0; u < 8; ++u)
        #pragma unroll
        for (int j = 0; j < 8; ++j) acc[u][j] = 0.f;

    #pragma unroll 4
    for (int c = 0; c < CC; ++c) {
        float4 w0 = *(float4*)&wt[c * XS_S + r0];
        float4 w1 = *(float4*)&wt[c * XS_S + r0 + 4];
        float4 x0 = *(float4*)&xs[c * XS_S + p0];
        float4 x1 = *(float4*)&xs[c * XS_S + p0 + 4];
        float wv[8] = {w0.x,w0.y,w0.z,w0.w,w1.x,w1.y,w1.z,w1.w};
        float xv[8] = {x0.x,x0.y,x0.z,x0.w,x1.x,x1.y,x1.z,x1.w};
        #pragma unroll
        for (int u = 0; u < 8; ++u)
            #pragma unroll
            for (int j = 0; j < 8; ++j)
                acc[u][j] = fmaf(wv[u], xv[j], acc[u][j]);
    }

    const float s2 = 0.17677669529663689f * 1.4426950408889634f;  // 1/sqrt(32)*log2(e)

    if (r0 < CC2) {
        // q: [p][c], c-range r0..r0+7 -> one uint4 per point
        #pragma unroll
        for (int j = 0; j < 8; ++j) {
            uint4 hv;
            hv.x = h2_u32(__floats2half2_rn(acc[0][j]*s2, acc[1][j]*s2));
            hv.y = h2_u32(__floats2half2_rn(acc[2][j]*s2, acc[3][j]*s2));
            hv.z = h2_u32(__floats2half2_rn(acc[4][j]*s2, acc[5][j]*s2));
            hv.w = h2_u32(__floats2half2_rn(acc[6][j]*s2, acc[7][j]*s2));
            *(uint4*)&g_q[((size_t)bt * PP + p0g + p0 + j) * CC2 + r0] = hv;
        }
    } else if (r0 < 2 * CC2) {
        #pragma unroll
        for (int j = 0; j < 8; ++j) {
            uint4 hv;
            hv.x = h2_u32(__floats2half2_rn(acc[0][j], acc[1][j]));
            hv.y = h2_u32(__floats2half2_rn(acc[2][j], acc[3][j]));
            hv.z = h2_u32(__floats2half2_rn(acc[4][j], acc[5][j]));
            hv.w = h2_u32(__floats2half2_rn(acc[6][j], acc[7][j]));
            *(uint4*)&g_k[((size_t)bt * PP + p0g + p0 + j) * CC2 + r0 - CC2] = hv;
        }
    } else {
        // v: [o][p], 8 consecutive points -> one uint4 per o-row
        #pragma unroll
        for (int u = 0; u < 8; ++u) {
            uint4 hv;
            hv.x = h2_u32(__floats2half2_rn(acc[u][0], acc[u][1]));
            hv.y = h2_u32(__floats2half2_rn(acc[u][2], acc[u][3]));
            hv.z = h2_u32(__floats2half2_rn(acc[u][4], acc[u][5]));
            hv.w = h2_u32(__floats2half2_rn(acc[u][6], acc[u][7]));
            *(uint4*)&g_vt[((size_t)bt * VROWS + r0 - 2 * CC2 + u) * PP + p0g + p0] = hv;
        }
    }

    // ones/zeros rows o=64..71 for this CTA's p-range
    if (tid < 128) {
        const int row = 64 + (tid >> 4), seg = tid & 15;
        const __half2 one2 = __floats2half2_rn(1.f, 1.f);
        const u32 fill = (row == 64) ? h2_u32(one2) : 0u;
        uint4 hv = make_uint4(fill, fill, fill, fill);
        *(uint4*)&g_vt[((size_t)bt * VROWS + row) * PP + p0g + seg * 8] = hv;
    }
}

// ---------------------------------------------------------------------------
// Kernel B: flash attention via mma.sync fp16, 256 threads, grid (18,16).
// S computed with f16 accumulation -> D-fragments feed h2exp2 directly
// (no cvt) and are already PV A-operands. Row sums via V ones-column.
// smem: Q @0 | K0 @10240 | K1 @20480 | V0 @30720 | V1 @50304. total 69888.
// ---------------------------------------------------------------------------
#define QK_STB  80
#define VT_STB  272
#define SMB_Q   0
#define SMB_K0  10240
#define SMB_K1  20480
#define SMB_V0  30720
#define SMB_V1  50304
#define SMB_END 69888
#define OT_S    132

__global__ void __launch_bounds__(256)
flash_kernel(const float* __restrict__ x_in, float* __restrict__ out) {
    extern __shared__ char smem[];
    const u32 sb  = smem_u32(smem);
    const int tid  = threadIdx.x;
    const int w    = tid >> 5, lane = tid & 31;
    const int g    = lane >> 2, tq = lane & 3;
    const int lm   = lane >> 3, lr = lane & 7;
    const int bt   = blockIdx.y, b = bt >> 3, t = bt & 7;
    const int q0   = blockIdx.x * 128;

    const __half* gqb = &g_q[(size_t)bt * PP * CC2];
    const __half* gkb = &g_k[(size_t)bt * PP * CC2];
    const __half* gvb = &g_vt[(size_t)bt * VROWS * PP];

    // ---- initial stage: Q tile + K0 + V0 ----
    {
        #pragma unroll
        for (int j = 0; j < 2; ++j) {
            int idx = tid + j * 256;
            int row = idx >> 2, col = idx & 3;
            CP16(sb + SMB_Q  + row * QK_STB + col * 16, gqb + (size_t)(q0 + row) * CC2 + col * 8);
            CP16(sb + SMB_K0 + row * QK_STB + col * 16, gkb + (size_t)row * CC2 + col * 8);
        }
        #pragma unroll
        for (int j = 0; j < 5; ++j) {
            int idx = tid + j * 256;
            if (idx < 1152) {
                int row = idx >> 4, col = idx & 15;
                CP16(sb + SMB_V0 + row * VT_STB + col * 16, gvb + (size_t)row * PP + col * 8);
            }
        }
    }
    CP_COMMIT(); CP_WAIT0();
    __syncthreads();

    // Q A-fragments (registers, whole kernel)
    u32 aq[2][4];
    {
        const u32 qb = sb + SMB_Q + (w * 16 + (lm & 1) * 8 + lr) * QK_STB + (lm >> 1) * 16;
        LDSM4(aq[0], qb);
        LDSM4(aq[1], qb + 32);
    }

    float o[9][4];
    #pragma unroll
    for (int i = 0; i < 9; ++i)
        #pragma unroll
        for (int j = 0; j < 4; ++j) o[i][j] = 0.f;

    const u32 kldb[2] = { sb + SMB_K0 + lr * QK_STB + lm * 16,
                          sb + SMB_K1 + lr * QK_STB + lm * 16 };
    const u32 vldb[2] = { sb + SMB_V0 + lr * VT_STB + lm * 16,
                          sb + SMB_V1 + lr * VT_STB + lm * 16 };

    for (int kt = 0; kt < NTILE; ++kt) {
        const int cb = kt & 1, nb = cb ^ 1;
        const bool more = (kt + 1 < NTILE);

        // prefetch next K/V tile into the other buffer
        if (more) {
            const int k0 = (kt + 1) * 128;
            const u32 kdst = sb + (nb ? SMB_K1 : SMB_K0);
            const u32 vdst = sb + (nb ? SMB_V1 : SMB_V0);
            #pragma unroll
            for (int j = 0; j < 2; ++j) {
                int idx = tid + j * 256;
                int row = idx >> 2, col = idx & 3;
                CP16(kdst + row * QK_STB + col * 16, gkb + (size_t)(k0 + row) * CC2 + col * 8);
            }
            #pragma unroll
            for (int j = 0; j < 5; ++j) {
                int idx = tid + j * 256;
                if (idx < 1152) {
                    int row = idx >> 4, col = idx & 15;
                    CP16(vdst + row * VT_STB + col * 16, gvb + (size_t)row * PP + k0 + col * 8);
                }
            }
            CP_COMMIT();
        }

        // ---- S = Q K^T (f16 accum) fused with exp2: P emerges packed ----
        u32 pf[16][2];
        #pragma unroll
        for (int nf = 0; nf < 16; ++nf) {
            u32 kb[4];
            LDSM4(kb, kldb[cb] + nf * 8 * QK_STB);
            u32 d[2] = {0u, 0u};
            MMAF16H(d, aq[0][0], aq[0][1], aq[0][2], aq[0][3], kb[0], kb[1]);
            MMAF16H(d, aq[1][0], aq[1][1], aq[1][2], aq[1][3], kb[2], kb[3]);
            pf[nf][0] = h2_u32(h2exp2(*(__half2*)&d[0]));
            pf[nf][1] = h2_u32(h2exp2(*(__half2*)&d[1]));
        }

        // ---- O += P V : 9 o-groups (last = ones column -> row sums) ----
        #pragma unroll
        for (int nf2 = 0; nf2 < 9; ++nf2) {
            #pragma unroll
            for (int kp = 0; kp < 4; ++kp) {
                u32 vb[4];
                LDSM4(vb, vldb[cb] + nf2 * 8 * VT_STB + kp * 64);
                MMAF16(o[nf2], pf[4*kp][0], pf[4*kp][1], pf[4*kp+1][0], pf[4*kp+1][1], vb[0], vb[1]);
                MMAF16(o[nf2], pf[4*kp+2][0], pf[4*kp+2][1], pf[4*kp+3][0], pf[4*kp+3][1], vb[2], vb[3]);
            }
        }

        CP_WAIT0();
        __syncthreads();
    }

    // ---- row sums from ones-column (col 64 lives in tq==0 lanes) ----
    const int qlead = lane & 28;
    const float inv_lo = 1.f / __shfl_sync(0xffffffffu, o[8][0], qlead);
    const float inv_hi = 1.f / __shfl_sync(0xffffffffu, o[8][2], qlead);

    float* ot = (float*)smem;
    const int prow = w * 16 + g;
    #pragma unroll
    for (int nf2 = 0; nf2 < 8; ++nf2) {
        int oc = nf2 * 8 + 2 * tq;
        ot[(oc    ) * OT_S + prow    ] = o[nf2][0] * inv_lo;
        ot[(oc + 1) * OT_S + prow    ] = o[nf2][1] * inv_lo;
        ot[(oc    ) * OT_S + prow + 8] = o[nf2][2] * inv_hi;
        ot[(oc + 1) * OT_S + prow + 8] = o[nf2][3] * inv_hi;
    }
    __syncthreads();

    // out[b, o, t, q0 + p] = O^T + residual (coalesced float4)
    {
        const int oc = tid >> 2, qt = tid & 3;
        const size_t gb = ((size_t)(b * CC + oc) * TT + t) * PP + q0 + qt * 32;
        const float* src = &ot[oc * OT_S + qt * 32];
        #pragma unroll
        for (int j = 0; j < 8; ++j) {
            float4 v = *(const float4*)&src[4 * j];
            float4 x = *(const float4*)&x_in[gb + 4 * j];
            v.x += x.x; v.y += x.y; v.z += x.z; v.w += x.w;
            *(float4*)&out[gb + 4 * j] = v;
        }
    }
}

// ---------------------------------------------------------------------------

extern "C" void kernel_launch(void* const* d_in, const int* in_sizes, int n_in,
                              void* d_out, int out_size) {
    const float* x_in = (const float*)d_in[0];
    const float* thw  = (const float*)d_in[1];
    const float* phw  = (const float*)d_in[2];
    const float* ow   = (const float*)d_in[3];
    float* out = (float*)d_out;

    const int prep_smem  = 2 * CC * XS_S * 4;  // 67584 B
    const int flash_smem = SMB_END;            // 69888 B

    cudaFuncSetAttribute(prep_kernel,  cudaFuncAttributeMaxDynamicSharedMemorySize, prep_smem);
    cudaFuncSetAttribute(flash_kernel, cudaFuncAttributeMaxDynamicSharedMemorySize, flash_smem);

    prep_kernel<<<dim3(NBT, PP / 128), 256, prep_smem>>>(x_in, thw, phw, ow);
    flash_kernel<<<dim3(PP / 128, NBT), 256, flash_smem>>>(x_in, out);
}